// round 2
// baseline (speedup 1.0000x reference)
#include <cuda_runtime.h>
#include <cuda_bf16.h>
#include <math.h>

#define NN   50000
#define EE   600000
#define HH   128
#define INF  7
#define OUTF 4
#define NL   4

// ---------------- scratch (allocation-free: __device__ globals) ----------------
__device__ float g_zA[NN * HH];
__device__ float g_zB[NN * HH];
__device__ float g_agg[NN * HH];
__device__ int   g_deg[NN];
__device__ int   g_scan[NN];
__device__ int   g_rowptr[NN + 1];
__device__ int   g_fill[NN];
__device__ int   g_col[EE];
__device__ float g_invdeg[NN];
__device__ int   g_bsum[64];
__device__ int   g_boff[64];
__device__ float g_bnsum[HH];
__device__ float g_bnsq[HH];
__device__ float g_scale[HH];
__device__ float g_shift[HH];
__device__ int   g_is64;

// ---------------- edge-index dtype probe ----------------
// int64 little-endian values < 2^31 have zero high words; int32 layout has
// random indices there. 16 consecutive zeros => int64 (P(false pos) ~ 5e-76).
__global__ void k_detect(const int* __restrict__ ei32) {
    if (threadIdx.x == 0) {
        int z = 0;
#pragma unroll
        for (int i = 0; i < 16; i++) z |= ei32[2 * i + 1];
        g_is64 = (z == 0) ? 1 : 0;
    }
}

__device__ __forceinline__ int clampN(int v) {
    v = v < 0 ? 0 : v;
    return v >= NN ? NN - 1 : v;
}
__device__ __forceinline__ int edge_src(const void* ei, int e) {
    int v = g_is64 ? (int)((const long long*)ei)[e] : ((const int*)ei)[e];
    return clampN(v);
}
__device__ __forceinline__ int edge_dst(const void* ei, int e) {
    int v = g_is64 ? (int)((const long long*)ei)[EE + e] : ((const int*)ei)[EE + e];
    return clampN(v);
}

// ---------------- CSR build ----------------
__global__ void k_degree(const void* __restrict__ ei) {
    int e = blockIdx.x * blockDim.x + threadIdx.x;
    if (e < EE) atomicAdd(&g_deg[edge_dst(ei, e)], 1);
}

__global__ void k_scan1() {
    __shared__ int wsum[32];
    int i = blockIdx.x * 1024 + threadIdx.x;
    int v = (i < NN) ? g_deg[i] : 0;
    int lane = threadIdx.x & 31, wid = threadIdx.x >> 5;
    int x = v;
#pragma unroll
    for (int d = 1; d < 32; d <<= 1) {
        int y = __shfl_up_sync(0xFFFFFFFFu, x, d);
        if (lane >= d) x += y;
    }
    if (lane == 31) wsum[wid] = x;
    __syncthreads();
    if (wid == 0) {
        int s = wsum[lane];
#pragma unroll
        for (int d = 1; d < 32; d <<= 1) {
            int y = __shfl_up_sync(0xFFFFFFFFu, s, d);
            if (lane >= d) s += y;
        }
        wsum[lane] = s;
    }
    __syncthreads();
    int off = (wid > 0) ? wsum[wid - 1] : 0;
    int incl = x + off;
    if (i < NN) g_scan[i] = incl;
    if (threadIdx.x == 1023) g_bsum[blockIdx.x] = incl;
}

__global__ void k_scan2(int nblk) {
    if (threadIdx.x == 0 && blockIdx.x == 0) {
        int run = 0;
        for (int b = 0; b < nblk; b++) { int t = g_bsum[b]; g_boff[b] = run; run += t; }
    }
}

__global__ void k_scan3() {
    int i = blockIdx.x * blockDim.x + threadIdx.x;
    if (i < NN) {
        g_rowptr[i + 1] = g_scan[i] + g_boff[i >> 10];
        if (i == 0) g_rowptr[0] = 0;
        g_fill[i] = 0;
        int d = g_deg[i];
        g_invdeg[i] = 1.0f / (float)(d > 1 ? d : 1);
    }
}

__global__ void k_scatter(const void* __restrict__ ei) {
    int e = blockIdx.x * blockDim.x + threadIdx.x;
    if (e < EE) {
        int dst = edge_dst(ei, e);
        int src = edge_src(ei, e);
        int p = g_rowptr[dst] + atomicAdd(&g_fill[dst], 1);
        g_col[p] = src;
    }
}

// ---------------- encoder: z = x @ enc_W + enc_b ----------------
__global__ void k_enc(const float* __restrict__ x, const float* __restrict__ eW,
                      const float* __restrict__ eb, float* __restrict__ z) {
    __shared__ float W[INF * HH];
    for (int i = threadIdx.x; i < INF * HH; i += blockDim.x) W[i] = eW[i];
    __syncthreads();
    int idx = blockIdx.x * blockDim.x + threadIdx.x;
    if (idx >= NN * HH) return;
    int n = idx >> 7, h = idx & 127;
    float s = eb[h];
    const float* xr = x + n * INF;
#pragma unroll
    for (int k = 0; k < INF; k++) s = fmaf(xr[k], W[k * HH + h], s);
    z[idx] = s;
}

// ---------------- aggregation: warp per node, CSR gather-mean ----------------
__global__ void k_agg(const float* __restrict__ zin, float* __restrict__ agg) {
    int w = (blockIdx.x * blockDim.x + threadIdx.x) >> 5;
    int lane = threadIdx.x & 31;
    if (w >= NN) return;
    int beg = g_rowptr[w], end = g_rowptr[w + 1];
    float4 acc = make_float4(0.f, 0.f, 0.f, 0.f);
    for (int j = beg; j < end; j++) {
        int s = g_col[j];
        float4 v = *(const float4*)&zin[s * HH + lane * 4];
        acc.x += v.x; acc.y += v.y; acc.z += v.z; acc.w += v.w;
    }
    float id = g_invdeg[w];
    acc.x *= id; acc.y *= id; acc.z *= id; acc.w *= id;
    *(float4*)&agg[w * HH + lane * 4] = acc;
}

// ---------------- GEMM: zout = agg @ Wl + zin @ Wr + b ----------------
// BM=64 rows/block, full N=128 cols, two K=128 stages (Wl/agg then Wr/zin).
// smem: Ws[128][128] + As[64][128] = 96KB -> 2 CTAs/SM.
#define BM 64
__global__ void __launch_bounds__(256, 2)
k_gemm(const float* __restrict__ agg, const float* __restrict__ zin,
       const float* __restrict__ Wl, const float* __restrict__ Wr,
       const float* __restrict__ bias, float* __restrict__ zout) {
    extern __shared__ float sm[];
    float* Ws = sm;              // 128*128
    float* As = sm + HH * HH;    // BM*128
    const int t = threadIdx.x;
    const int cg = t & 31, rg = t >> 5;   // warp = rg (row group), lane = cg (col group)
    const int c0 = cg * 4;
    const int row0 = blockIdx.x * BM;

    float acc[8][4];
#pragma unroll
    for (int r = 0; r < 8; r++)
#pragma unroll
        for (int c = 0; c < 4; c++) acc[r][c] = 0.f;

#pragma unroll
    for (int s = 0; s < 2; s++) {
        const float* W = s ? Wr : Wl;
        const float* A = s ? zin : agg;
        // stage W into smem (float4)
        for (int i = t; i < HH * HH / 4; i += 256)
            ((float4*)Ws)[i] = ((const float4*)W)[i];
        // stage A tile
        for (int i = t; i < BM * HH / 4; i += 256) {
            int r = i >> 5, k4 = i & 31;
            int gr = row0 + r;
            float4 v = make_float4(0.f, 0.f, 0.f, 0.f);
            if (gr < NN) v = ((const float4*)(A + (size_t)gr * HH))[k4];
            ((float4*)As)[i] = v;
        }
        __syncthreads();
#pragma unroll 2
        for (int k0 = 0; k0 < HH; k0 += 4) {
            float4 w0 = *(const float4*)&Ws[(k0 + 0) * HH + c0];
            float4 w1 = *(const float4*)&Ws[(k0 + 1) * HH + c0];
            float4 w2 = *(const float4*)&Ws[(k0 + 2) * HH + c0];
            float4 w3 = *(const float4*)&Ws[(k0 + 3) * HH + c0];
#pragma unroll
            for (int rr = 0; rr < 8; rr++) {
                float4 a = *(const float4*)&As[(rg * 8 + rr) * HH + k0];
                acc[rr][0] = fmaf(a.x, w0.x, fmaf(a.y, w1.x, fmaf(a.z, w2.x, fmaf(a.w, w3.x, acc[rr][0]))));
                acc[rr][1] = fmaf(a.x, w0.y, fmaf(a.y, w1.y, fmaf(a.z, w2.y, fmaf(a.w, w3.y, acc[rr][1]))));
                acc[rr][2] = fmaf(a.x, w0.z, fmaf(a.y, w1.z, fmaf(a.z, w2.z, fmaf(a.w, w3.z, acc[rr][2]))));
                acc[rr][3] = fmaf(a.x, w0.w, fmaf(a.y, w1.w, fmaf(a.z, w2.w, fmaf(a.w, w3.w, acc[rr][3]))));
            }
        }
        __syncthreads();
    }

    float4 bb = *(const float4*)&bias[c0];
#pragma unroll
    for (int rr = 0; rr < 8; rr++) {
        int gr = row0 + rg * 8 + rr;
        if (gr < NN) {
            float4 o;
            o.x = acc[rr][0] + bb.x;
            o.y = acc[rr][1] + bb.y;
            o.z = acc[rr][2] + bb.z;
            o.w = acc[rr][3] + bb.w;
            *(float4*)&zout[(size_t)gr * HH + c0] = o;
        }
    }
}

// ---------------- BatchNorm ----------------
__global__ void k_bnstats(const float* __restrict__ z) {
    int h = threadIdx.x;              // 128 threads = columns
    int r0 = blockIdx.x * 256;
    int rend = r0 + 256; if (rend > NN) rend = NN;
    float s = 0.f, ss = 0.f;
    for (int r = r0; r < rend; r++) {
        float v = z[r * HH + h];
        s += v; ss = fmaf(v, v, ss);
    }
    atomicAdd(&g_bnsum[h], s);
    atomicAdd(&g_bnsq[h], ss);
}

__global__ void k_bnfin(const float* __restrict__ gamma, const float* __restrict__ beta) {
    int h = threadIdx.x;
    float inv = 1.0f / (float)NN;
    float mu = g_bnsum[h] * inv;
    float var = g_bnsq[h] * inv - mu * mu;
    float sc = gamma[h] * rsqrtf(var + 1e-5f);
    g_scale[h] = sc;
    g_shift[h] = beta[h] - mu * sc;
}

__global__ void k_bnapply(float* __restrict__ z) {
    int i = blockIdx.x * blockDim.x + threadIdx.x;
    if (i >= NN * (HH / 4)) return;
    int h4 = i & 31;
    float4 v = ((float4*)z)[i];
    float4 sc = ((const float4*)g_scale)[h4];
    float4 sh = ((const float4*)g_shift)[h4];
    v.x = fmaxf(fmaf(v.x, sc.x, sh.x), 0.f);
    v.y = fmaxf(fmaf(v.y, sc.y, sh.y), 0.f);
    v.z = fmaxf(fmaf(v.z, sc.z, sh.z), 0.f);
    v.w = fmaxf(fmaf(v.w, sc.w, sh.w), 0.f);
    ((float4*)z)[i] = v;
}

// ---------------- decoder: out = z @ dec_W + dec_b ----------------
__global__ void k_dec(const float* __restrict__ z, const float* __restrict__ dW,
                      const float* __restrict__ db, float* __restrict__ out) {
    __shared__ float W[HH * OUTF];
    for (int i = threadIdx.x; i < HH * OUTF; i += blockDim.x) W[i] = dW[i];
    __syncthreads();
    int w = (blockIdx.x * blockDim.x + threadIdx.x) >> 5;
    int lane = threadIdx.x & 31;
    if (w >= NN) return;
    float4 zv = *(const float4*)&z[w * HH + lane * 4];
    int h = lane * 4;
    float o0 = zv.x * W[h * 4 + 0] + zv.y * W[(h + 1) * 4 + 0] + zv.z * W[(h + 2) * 4 + 0] + zv.w * W[(h + 3) * 4 + 0];
    float o1 = zv.x * W[h * 4 + 1] + zv.y * W[(h + 1) * 4 + 1] + zv.z * W[(h + 2) * 4 + 1] + zv.w * W[(h + 3) * 4 + 1];
    float o2 = zv.x * W[h * 4 + 2] + zv.y * W[(h + 1) * 4 + 2] + zv.z * W[(h + 2) * 4 + 2] + zv.w * W[(h + 3) * 4 + 2];
    float o3 = zv.x * W[h * 4 + 3] + zv.y * W[(h + 1) * 4 + 3] + zv.z * W[(h + 2) * 4 + 3] + zv.w * W[(h + 3) * 4 + 3];
#pragma unroll
    for (int d = 16; d; d >>= 1) {
        o0 += __shfl_down_sync(0xFFFFFFFFu, o0, d);
        o1 += __shfl_down_sync(0xFFFFFFFFu, o1, d);
        o2 += __shfl_down_sync(0xFFFFFFFFu, o2, d);
        o3 += __shfl_down_sync(0xFFFFFFFFu, o3, d);
    }
    if (lane == 0) {
        float4 r;
        r.x = o0 + db[0]; r.y = o1 + db[1]; r.z = o2 + db[2]; r.w = o3 + db[3];
        *(float4*)&out[w * 4] = r;
    }
}

// ---------------- launch ----------------
extern "C" void kernel_launch(void* const* d_in, const int* in_sizes, int n_in,
                              void* d_out, int out_size) {
    const float* x      = (const float*)d_in[0];
    const float* enc_W  = (const float*)d_in[1];
    const float* enc_b  = (const float*)d_in[2];
    const float* Wl     = (const float*)d_in[3];   // [4][128][128]
    const float* Wr     = (const float*)d_in[4];
    const float* b      = (const float*)d_in[5];   // [4][128]
    const float* bng    = (const float*)d_in[6];   // [3][128]
    const float* bnb    = (const float*)d_in[7];
    const float* dec_W  = (const float*)d_in[8];
    const float* dec_b  = (const float*)d_in[9];
    const void*  ei     = d_in[10];                // [2][E] int32 (or int64; probed)
    float* out = (float*)d_out;

    float *zA, *zB, *agg;
    void* p;
    cudaGetSymbolAddress(&p, g_zA);  zA  = (float*)p;
    cudaGetSymbolAddress(&p, g_zB);  zB  = (float*)p;
    cudaGetSymbolAddress(&p, g_agg); agg = (float*)p;
    void *pdeg, *pbnsum, *pbnsq;
    cudaGetSymbolAddress(&pdeg, g_deg);
    cudaGetSymbolAddress(&pbnsum, g_bnsum);
    cudaGetSymbolAddress(&pbnsq, g_bnsq);

    const size_t GEMM_SMEM = (size_t)(HH * HH + BM * HH) * sizeof(float); // 96 KB
    cudaFuncSetAttribute(k_gemm, cudaFuncAttributeMaxDynamicSharedMemorySize, (int)GEMM_SMEM);

    const int TB = 256;
    const int egrid = (EE + TB - 1) / TB;

    // CSR build
    k_detect<<<1, 32>>>((const int*)ei);
    cudaMemsetAsync(pdeg, 0, NN * sizeof(int));
    k_degree<<<egrid, TB>>>(ei);
    k_scan1<<<(NN + 1023) / 1024, 1024>>>();
    k_scan2<<<1, 32>>>((NN + 1023) / 1024);
    k_scan3<<<(NN + TB - 1) / TB, TB>>>();
    k_scatter<<<egrid, TB>>>(ei);

    // encoder
    k_enc<<<(NN * HH + TB - 1) / TB, TB>>>(x, enc_W, enc_b, zA);

    float* zin = zA;
    float* zout = zB;
    for (int i = 0; i < NL; i++) {
        k_agg<<<(NN * 32 + TB - 1) / TB, TB>>>(zin, agg);
        k_gemm<<<(NN + BM - 1) / BM, TB, GEMM_SMEM>>>(agg, zin,
                Wl + (size_t)i * HH * HH, Wr + (size_t)i * HH * HH,
                b + (size_t)i * HH, zout);
        if (i < NL - 1) {
            cudaMemsetAsync(pbnsum, 0, HH * sizeof(float));
            cudaMemsetAsync(pbnsq, 0, HH * sizeof(float));
            k_bnstats<<<(NN + 255) / 256, HH>>>(zout);
            k_bnfin<<<1, HH>>>(bng + (size_t)i * HH, bnb + (size_t)i * HH);
            k_bnapply<<<(NN * (HH / 4) + TB - 1) / TB, TB>>>(zout);
        }
        float* tmp = zin; zin = zout; zout = tmp;
    }

    // after 4 layers, result is in zin
    k_dec<<<(NN * 32 + TB - 1) / TB, TB>>>(zin, dec_W, dec_b, out);
}